// round 8
// baseline (speedup 1.0000x reference)
#include <cuda_runtime.h>
#include <cstdint>

#define B_    8192
#define T_    90
#define F_    7
#define H_    128
#define G_    512      // 4*H
#define D1_   128
#define D2_   64
#define OUT_  30
#define KTOT  256      // H (x part) + H (h part)

// -------- device scratch (no cudaMalloc allowed) --------
__device__ float g_hin  [B_ * T_ * H_];   // LN(x@W_in^T+b) : layer-0 input
__device__ float g_hout0[B_ * T_ * H_];   // layer-0 hidden outputs
__device__ float g_WT   [2 * KTOT * G_];  // K-major packed [Wih|Whh] per layer
__device__ float g_biasC[2 * G_];         // bih + bhh per layer

// -------- helpers --------
__device__ __forceinline__ float sgf(float x) {
    return __fdividef(1.0f, 1.0f + __expf(-x));
}
__device__ __forceinline__ float thf(float x) {
    return 2.0f * sgf(2.0f * x) - 1.0f;
}
__device__ __forceinline__ unsigned long long pk2(float x) {
    unsigned long long r;
    asm("mov.b64 %0, {%1, %1};" : "=l"(r) : "f"(x));
    return r;
}
__device__ __forceinline__ unsigned long long pkab(float a, float b) {
    unsigned long long r;
    asm("mov.b64 %0, {%1, %2};" : "=l"(r) : "f"(a), "f"(b));
    return r;
}
__device__ __forceinline__ void up2(unsigned long long v, float& a, float& b) {
    asm("mov.b64 {%0, %1}, %2;" : "=f"(a), "=f"(b) : "l"(v));
}
// packed dual fp32 FMA (sm_100+): d = a*b + d  (lane-wise on the two f32 halves)
__device__ __forceinline__ void fma2(unsigned long long& d,
                                     unsigned long long a, unsigned long long b) {
    asm("fma.rn.f32x2 %0, %1, %2, %0;" : "+l"(d) : "l"(a), "l"(b));
}
__device__ __forceinline__ void cpa16(uint32_t s, const void* g) {
    asm volatile("cp.async.cg.shared.global [%0], [%1], 16;" :: "r"(s), "l"(g));
}
__device__ __forceinline__ void cpcommit() { asm volatile("cp.async.commit_group;"); }
__device__ __forceinline__ void cpwait0()  { asm volatile("cp.async.wait_group 0;"); }

// ======================= K0: weight repack =======================
__global__ void prep_kernel(const float* __restrict__ Wih0, const float* __restrict__ Whh0,
                            const float* __restrict__ bih0, const float* __restrict__ bhh0,
                            const float* __restrict__ Wih1, const float* __restrict__ Whh1,
                            const float* __restrict__ bih1, const float* __restrict__ bhh1) {
    int idx = blockIdx.x * blockDim.x + threadIdx.x;
    int tot = 2 * KTOT * G_;
    if (idx < tot) {
        int L = idx / (KTOT * G_);
        int r = idx % (KTOT * G_);
        int k = r / G_;
        int n = r % G_;
        const float* Wih = L ? Wih1 : Wih0;
        const float* Whh = L ? Whh1 : Whh0;
        g_WT[idx] = (k < H_) ? Wih[n * H_ + k] : Whh[n * H_ + (k - H_)];
    }
    if (idx < 2 * G_) {
        int L = idx / G_;
        int n = idx % G_;
        g_biasC[idx] = L ? (bih1[n] + bhh1[n]) : (bih0[n] + bhh0[n]);
    }
}

// ============ K1: input projection + layernorm (warp per row) ============
__global__ void __launch_bounds__(256) proj_ln_kernel(
    const float* __restrict__ x, const float* __restrict__ W_in,
    const float* __restrict__ b_in, const float* __restrict__ g_in,
    const float* __restrict__ be_in) {
    __shared__ float Ws[H_ * F_];
    __shared__ float bs[H_], gs[H_], es[H_];
    int tid = threadIdx.x;
    for (int i = tid; i < H_ * F_; i += 256) Ws[i] = W_in[i];
    if (tid < H_) { bs[tid] = b_in[tid]; gs[tid] = g_in[tid]; es[tid] = be_in[tid]; }
    __syncthreads();

    int warp = tid >> 5, lane = tid & 31;
    int row = blockIdx.x * 8 + warp;        // row < B*T = 737280

    float xv = (lane < F_) ? x[row * F_ + lane] : 0.0f;
    float y[4];
#pragma unroll
    for (int j = 0; j < 4; j++) {
        int h = lane + 32 * j;
        float a = bs[h];
#pragma unroll
        for (int f = 0; f < F_; f++) {
            float xf = __shfl_sync(0xffffffffu, xv, f);
            a = fmaf(xf, Ws[h * F_ + f], a);
        }
        y[j] = a;
    }
    float s = y[0] + y[1] + y[2] + y[3];
#pragma unroll
    for (int o = 16; o; o >>= 1) s += __shfl_xor_sync(0xffffffffu, s, o);
    float mu = s * (1.0f / H_);
    float v = 0.0f;
#pragma unroll
    for (int j = 0; j < 4; j++) { float d = y[j] - mu; v += d * d; }
#pragma unroll
    for (int o = 16; o; o >>= 1) v += __shfl_xor_sync(0xffffffffu, v, o);
    float rstd = rsqrtf(v * (1.0f / H_) + 1e-5f);
#pragma unroll
    for (int j = 0; j < 4; j++) {
        int h = lane + 32 * j;
        g_hin[row * H_ + h] = (y[j] - mu) * rstd * gs[h] + es[h];
    }
}

// ============ K2: persistent 2-layer LSTM + LN + dense head ============
// 128 CTAs x 256 threads; each CTA owns 64 batch rows end-to-end.
// smem layout (dynamic):
//   [0, 65536)            aT      : float[256][64]  (k-major activations: x | h)
//   [65536, 196608)       wbuf0/1 : two 32x512 float weight chunks
//   [196608, 198656)      biasS   : float[512]
// dense-phase reuse inside the wbuf region.
#define OFF_AT   0
#define OFF_W0   65536
#define OFF_W1   (65536 + 65536)
#define OFF_BIAS 196608
#define SMEM_BYTES 198656

__global__ void __launch_bounds__(256, 1) lstm_kernel(
    const float* __restrict__ g_ln, const float* __restrict__ be_ln,
    const float* __restrict__ W_d1, const float* __restrict__ b_d1,
    const float* __restrict__ W_d2, const float* __restrict__ b_d2,
    const float* __restrict__ W_d3, const float* __restrict__ b_d3,
    float* __restrict__ out) {
    extern __shared__ char smem[];
    float* aT    = (float*)(smem + OFF_AT);
    float* wbuf0 = (float*)(smem + OFF_W0);
    float* wbuf1 = (float*)(smem + OFF_W1);
    float* biasS = (float*)(smem + OFF_BIAS);

    const int tid = threadIdx.x;
    const int tr  = tid & 15;   // row group: rows 4*tr .. 4*tr+3
    const int tc  = tid >> 4;   // 0..15: cols [tc*8, tc*8+8) within each gate
    const int row0 = blockIdx.x * 64;

    uint32_t wsmAddr[2];
    wsmAddr[0] = (uint32_t)__cvta_generic_to_shared(wbuf0);
    wsmAddr[1] = (uint32_t)__cvta_generic_to_shared(wbuf1);

    unsigned long long c2[4][4];        // cell state pairs (regs)
    unsigned long long acc[4][4][4];    // gate accum: [row][gate][pair]

    for (int layer = 0; layer < 2; ++layer) {
        const float* xin = layer ? g_hout0 : g_hin;
        const float* WT  = g_WT + layer * (KTOT * G_);

        __syncthreads();    // previous phase fully done before reinit
        for (int i = tid; i < G_; i += 256) biasS[i] = g_biasC[layer * G_ + i];
        for (int i = tid; i < H_ * 64; i += 256) aT[H_ * 64 + i] = 0.0f;  // h = 0
#pragma unroll
        for (int i = 0; i < 4; i++)
#pragma unroll
            for (int p = 0; p < 4; p++) c2[i][p] = 0ull;

        for (int t = 0; t < T_; ++t) {
            __syncthreads();   // A: prior-step readers/writers done
            // ---- load x_t transposed into aT[0..127][row] ----
            {
                int r = tid >> 2;
                int seg = (tid & 3) * 32;
                const float* src = xin + ((row0 + r) * T_ + t) * H_ + seg;
#pragma unroll
                for (int j = 0; j < 8; j++) {
                    float4 v = *(const float4*)(src + j * 4);
                    int k = seg + j * 4;
                    aT[(k + 0) * 64 + r] = v.x;
                    aT[(k + 1) * 64 + r] = v.y;
                    aT[(k + 2) * 64 + r] = v.z;
                    aT[(k + 3) * 64 + r] = v.w;
                }
            }
            __syncthreads();   // B: x ready

#pragma unroll
            for (int i = 0; i < 4; i++)
#pragma unroll
                for (int g = 0; g < 4; g++)
#pragma unroll
                    for (int p = 0; p < 4; p++) acc[i][g][p] = 0ull;

            // ---- K loop: 8 chunks of 32 k-values, double-buffered cp.async ----
            auto issue_copy = [&](int ck) {
                const float* src = WT + ck * (32 * G_);
                uint32_t sb = wsmAddr[ck & 1];
#pragma unroll
                for (int j = 0; j < 16; j++) {
                    int u = tid + 256 * j;
                    cpa16(sb + u * 16, src + u * 4);
                }
                cpcommit();
            };
            issue_copy(0);
            const int tc2 = tc * 2;
            for (int ck = 0; ck < 8; ++ck) {
                cpwait0();
                __syncthreads();
                if (ck < 7) issue_copy(ck + 1);
                const float* wb  = (ck & 1) ? wbuf1 : wbuf0;
                const float* aTk = aT + ck * (32 * 64);
#pragma unroll 4
                for (int kk = 0; kk < 32; ++kk) {
                    const float4 a4 = *(const float4*)(aTk + kk * 64 + tr * 4);
                    unsigned long long a2[4] = {pk2(a4.x), pk2(a4.y), pk2(a4.z), pk2(a4.w)};
                    const ulonglong2* wr = (const ulonglong2*)(wb + kk * G_);
#pragma unroll
                    for (int g = 0; g < 4; ++g) {
                        ulonglong2 wA = wr[g * 32 + tc2];
                        ulonglong2 wB = wr[g * 32 + tc2 + 1];
#pragma unroll
                        for (int i = 0; i < 4; ++i) {
                            fma2(acc[i][g][0], a2[i], wA.x);
                            fma2(acc[i][g][1], a2[i], wA.y);
                            fma2(acc[i][g][2], a2[i], wB.x);
                            fma2(acc[i][g][3], a2[i], wB.y);
                        }
                    }
                }
            }
            __syncthreads();   // all GEMM reads of aT done before h overwrite

            // ---- activations + state update (regs) ----
            const unsigned long long* b2 = (const unsigned long long*)biasS;
#pragma unroll
            for (int i = 0; i < 4; i++) {
                int r = tr * 4 + i;
                float hv[8];
#pragma unroll
                for (int p = 0; p < 4; p++) {
                    int pi = tc * 4 + p;    // pair index within a gate (col = 2*pi)
                    float iv0, iv1, fv0, fv1, gv0, gv1, ov0, ov1, b0, b1;
                    up2(acc[i][0][p], iv0, iv1); up2(b2[0 * 64 + pi], b0, b1); iv0 += b0; iv1 += b1;
                    up2(acc[i][1][p], fv0, fv1); up2(b2[1 * 64 + pi], b0, b1); fv0 += b0; fv1 += b1;
                    up2(acc[i][2][p], gv0, gv1); up2(b2[2 * 64 + pi], b0, b1); gv0 += b0; gv1 += b1;
                    up2(acc[i][3][p], ov0, ov1); up2(b2[3 * 64 + pi], b0, b1); ov0 += b0; ov1 += b1;
                    float c0, c1;
                    up2(c2[i][p], c0, c1);
                    c0 = sgf(fv0) * c0 + sgf(iv0) * thf(gv0);
                    c1 = sgf(fv1) * c1 + sgf(iv1) * thf(gv1);
                    c2[i][p] = pkab(c0, c1);
                    float h0 = sgf(ov0) * thf(c0);
                    float h1 = sgf(ov1) * thf(c1);
                    int col = tc * 8 + 2 * p;
                    aT[(H_ + col) * 64 + r]     = h0;
                    aT[(H_ + col + 1) * 64 + r] = h1;
                    hv[2 * p] = h0; hv[2 * p + 1] = h1;
                }
                if (layer == 0) {
                    float* dst = g_hout0 + ((row0 + r) * T_ + t) * H_ + tc * 8;
                    *(float4*)(dst)     = make_float4(hv[0], hv[1], hv[2], hv[3]);
                    *(float4*)(dst + 4) = make_float4(hv[4], hv[5], hv[6], hv[7]);
                }
            }
        } // t
    } // layer

    // =================== dense head (final h lives in aT) ===================
    __syncthreads();
    float* lnS = (float*)(smem + OFF_W0);                 // [64][128]
    float* d1S = (float*)(smem + OFF_W0 + 32768);         // [64][128]
    float* wdS = (float*)(smem + OFF_W0 + 65536);         // weight staging (64KB)
    float* d2S = lnS;                                     // reuse after LN dead

    // LayerNorm of last hidden state
    if (tid < 64) {
        int r = tid;
        float s = 0.0f;
        for (int k = 0; k < H_; k++) s += aT[(H_ + k) * 64 + r];
        float mu = s * (1.0f / H_);
        float v = 0.0f;
        for (int k = 0; k < H_; k++) { float d = aT[(H_ + k) * 64 + r] - mu; v += d * d; }
        float rstd = rsqrtf(v * (1.0f / H_) + 1e-5f);
        for (int k = 0; k < H_; k++)
            lnS[r * H_ + k] = (aT[(H_ + k) * 64 + r] - mu) * rstd * __ldg(g_ln + k) + __ldg(be_ln + k);
    }
    for (int i = tid; i < D1_ * H_ / 4; i += 256)
        ((float4*)wdS)[i] = ((const float4*)W_d1)[i];
    __syncthreads();

    // d1 = relu(ln @ W_d1^T + b_d1)
    {
        int r = tid >> 2, c0 = (tid & 3) * 32;
        for (int c = c0; c < c0 + 32; c++) {
            float a = __ldg(b_d1 + c);
            const float4* lp = (const float4*)(lnS + r * H_);
            const float4* wp = (const float4*)(wdS + c * H_);
#pragma unroll 8
            for (int k4 = 0; k4 < H_ / 4; k4++) {
                float4 l = lp[k4], w = wp[k4];
                a = fmaf(l.x, w.x, fmaf(l.y, w.y, fmaf(l.z, w.z, fmaf(l.w, w.w, a))));
            }
            d1S[r * D1_ + c] = fmaxf(a, 0.0f);
        }
    }
    __syncthreads();
    for (int i = tid; i < D2_ * D1_ / 4; i += 256)
        ((float4*)wdS)[i] = ((const float4*)W_d2)[i];
    float* w3S = wdS + D2_ * D1_;
    for (int i = tid; i < OUT_ * D2_; i += 256) w3S[i] = W_d3[i];
    __syncthreads();

    // d2 = relu(d1 @ W_d2^T + b_d2)
    {
        int r = tid >> 2, c0 = (tid & 3) * 16;
        for (int c = c0; c < c0 + 16; c++) {
            float a = __ldg(b_d2 + c);
            const float4* dp = (const float4*)(d1S + r * D1_);
            const float4* wp = (const float4*)(wdS + c * D1_);
#pragma unroll 8
            for (int k4 = 0; k4 < D1_ / 4; k4++) {
                float4 l = dp[k4], w = wp[k4];
                a = fmaf(l.x, w.x, fmaf(l.y, w.y, fmaf(l.z, w.z, fmaf(l.w, w.w, a))));
            }
            d2S[r * D2_ + c] = fmaxf(a, 0.0f);
        }
    }
    __syncthreads();

    // out = d2 @ W_d3^T + b_d3
    for (int idx = tid; idx < 64 * OUT_; idx += 256) {
        int r = idx / OUT_, c = idx % OUT_;
        float a = __ldg(b_d3 + c);
        const float* dp = d2S + r * D2_;
        const float* wp = w3S + c * D2_;
#pragma unroll 8
        for (int k = 0; k < D2_; k++) a = fmaf(dp[k], wp[k], a);
        out[(row0 + r) * OUT_ + c] = a;
    }
}

// ======================= launch =======================
extern "C" void kernel_launch(void* const* d_in, const int* in_sizes, int n_in,
                              void* d_out, int out_size) {
    (void)in_sizes; (void)n_in; (void)out_size;
    const float* x     = (const float*)d_in[0];
    const float* W_in  = (const float*)d_in[1];
    const float* b_in  = (const float*)d_in[2];
    const float* g_in  = (const float*)d_in[3];
    const float* be_in = (const float*)d_in[4];
    const float* Wih0  = (const float*)d_in[5];
    const float* Whh0  = (const float*)d_in[6];
    const float* bih0  = (const float*)d_in[7];
    const float* bhh0  = (const float*)d_in[8];
    const float* Wih1  = (const float*)d_in[9];
    const float* Whh1  = (const float*)d_in[10];
    const float* bih1  = (const float*)d_in[11];
    const float* bhh1  = (const float*)d_in[12];
    const float* g_ln  = (const float*)d_in[13];
    const float* be_ln = (const float*)d_in[14];
    const float* W_d1  = (const float*)d_in[15];
    const float* b_d1  = (const float*)d_in[16];
    const float* W_d2  = (const float*)d_in[17];
    const float* b_d2  = (const float*)d_in[18];
    const float* W_d3  = (const float*)d_in[19];
    const float* b_d3  = (const float*)d_in[20];
    float* out = (float*)d_out;

    prep_kernel<<<1024, 256>>>(Wih0, Whh0, bih0, bhh0, Wih1, Whh1, bih1, bhh1);
    proj_ln_kernel<<<(B_ * T_) / 8, 256>>>(x, W_in, b_in, g_in, be_in);
    cudaFuncSetAttribute(lstm_kernel, cudaFuncAttributeMaxDynamicSharedMemorySize, SMEM_BYTES);
    lstm_kernel<<<B_ / 64, 256, SMEM_BYTES>>>(g_ln, be_ln, W_d1, b_d1, W_d2, b_d2,
                                              W_d3, b_d3, out);
}

// round 10
// speedup vs baseline: 1.4863x; 1.4863x over previous
#include <cuda_runtime.h>
#include <cstdint>
#include <cstddef>

#define B_    8192
#define T_    90
#define F_    7
#define H_    128
#define G_    512      // 4*H
#define D1_   128
#define D2_   64
#define OUT_  30

// -------- device scratch (no cudaMalloc allowed) --------
__device__ __align__(128) float g_hin  [(size_t)B_ * T_ * H_];   // LN(x@W_in^T+b), tf32-rounded
__device__ __align__(128) float g_hout0[(size_t)B_ * T_ * H_];   // layer-0 h outs, tf32-rounded
__device__ __align__(128) float g_xg   [(size_t)B_ * T_ * G_];   // input projections (+bias)
__device__ __align__(128) float g_WTh  [2 * H_ * G_];            // K-major packed Whh per layer
__device__ float g_biasC[2 * G_];                                // bih + bhh per layer

// ======================= common helpers =======================
__device__ __forceinline__ float sgf(float x) {
    return __fdividef(1.0f, 1.0f + __expf(-x));
}
__device__ __forceinline__ float thf(float x) {
    return 2.0f * sgf(2.0f * x) - 1.0f;
}
__device__ __forceinline__ float tf32r(float x) {
    uint32_t t;
    asm("cvt.rna.tf32.f32 %0, %1;" : "=r"(t) : "f"(x));
    return __uint_as_float(t);
}
__device__ __forceinline__ unsigned long long pk2(float x) {
    unsigned long long r;
    asm("mov.b64 %0, {%1, %1};" : "=l"(r) : "f"(x));
    return r;
}
__device__ __forceinline__ unsigned long long pkab(float a, float b) {
    unsigned long long r;
    asm("mov.b64 %0, {%1, %2};" : "=l"(r) : "f"(a), "f"(b));
    return r;
}
__device__ __forceinline__ void up2(unsigned long long v, float& a, float& b) {
    asm("mov.b64 {%0, %1}, %2;" : "=f"(a), "=f"(b) : "l"(v));
}
__device__ __forceinline__ void fma2(unsigned long long& d,
                                     unsigned long long a, unsigned long long b) {
    asm("fma.rn.f32x2 %0, %1, %2, %0;" : "+l"(d) : "l"(a), "l"(b));
}
__device__ __forceinline__ void cpa16(uint32_t s, const void* g) {
    asm volatile("cp.async.cg.shared.global [%0], [%1], 16;" :: "r"(s), "l"(g));
}
__device__ __forceinline__ void cpcommit() { asm volatile("cp.async.commit_group;"); }
__device__ __forceinline__ void cpwait0()  { asm volatile("cp.async.wait_group 0;"); }
__device__ __forceinline__ uint32_t smem_u32(const void* p) {
    uint32_t a;
    asm("{ .reg .u64 t; cvta.to.shared.u64 t, %1; cvt.u32.u64 %0, t; }" : "=r"(a) : "l"(p));
    return a;
}
// portable tensor-core mma (sm_80+ PTX, runs as HMMA on sm_103)
__device__ __forceinline__ void mma_tf32(float* d, const uint32_t* a, const uint32_t* b) {
    asm("mma.sync.aligned.m16n8k8.row.col.f32.tf32.tf32.f32 "
        "{%0,%1,%2,%3}, {%4,%5,%6,%7}, {%8,%9}, {%0,%1,%2,%3};"
        : "+f"(d[0]), "+f"(d[1]), "+f"(d[2]), "+f"(d[3])
        : "r"(a[0]), "r"(a[1]), "r"(a[2]), "r"(a[3]), "r"(b[0]), "r"(b[1]));
}

// ======================= K0: weight repack =======================
__global__ void prep_kernel(const float* __restrict__ Whh0, const float* __restrict__ bih0,
                            const float* __restrict__ bhh0, const float* __restrict__ Whh1,
                            const float* __restrict__ bih1, const float* __restrict__ bhh1) {
    int idx = blockIdx.x * blockDim.x + threadIdx.x;
    int tot = 2 * H_ * G_;
    if (idx < tot) {
        int L = idx / (H_ * G_);
        int r = idx % (H_ * G_);
        int k = r / G_;
        int n = r % G_;
        const float* Whh = L ? Whh1 : Whh0;
        g_WTh[idx] = Whh[n * H_ + k];
    }
    if (idx < 2 * G_) {
        int L = idx / G_;
        int n = idx % G_;
        g_biasC[idx] = L ? (bih1[n] + bhh1[n]) : (bih0[n] + bhh0[n]);
    }
}

// ============ K1: input projection + layernorm (warp per row) ============
__global__ void __launch_bounds__(256) proj_ln_kernel(
    const float* __restrict__ x, const float* __restrict__ W_in,
    const float* __restrict__ b_in, const float* __restrict__ g_in,
    const float* __restrict__ be_in) {
    __shared__ float Ws[H_ * F_];
    __shared__ float bs[H_], gs[H_], es[H_];
    int tid = threadIdx.x;
    for (int i = tid; i < H_ * F_; i += 256) Ws[i] = W_in[i];
    if (tid < H_) { bs[tid] = b_in[tid]; gs[tid] = g_in[tid]; es[tid] = be_in[tid]; }
    __syncthreads();

    int warp = tid >> 5, lane = tid & 31;
    int row = blockIdx.x * 8 + warp;

    float xv = (lane < F_) ? x[(size_t)row * F_ + lane] : 0.0f;
    float y[4];
#pragma unroll
    for (int j = 0; j < 4; j++) {
        int h = lane + 32 * j;
        float a = bs[h];
#pragma unroll
        for (int f = 0; f < F_; f++) {
            float xf = __shfl_sync(0xffffffffu, xv, f);
            a = fmaf(xf, Ws[h * F_ + f], a);
        }
        y[j] = a;
    }
    float s = y[0] + y[1] + y[2] + y[3];
#pragma unroll
    for (int o = 16; o; o >>= 1) s += __shfl_xor_sync(0xffffffffu, s, o);
    float mu = s * (1.0f / H_);
    float v = 0.0f;
#pragma unroll
    for (int j = 0; j < 4; j++) { float d = y[j] - mu; v += d * d; }
#pragma unroll
    for (int o = 16; o; o >>= 1) v += __shfl_xor_sync(0xffffffffu, v, o);
    float rstd = rsqrtf(v * (1.0f / H_) + 1e-5f);
#pragma unroll
    for (int j = 0; j < 4; j++) {
        int h = lane + 32 * j;
        // only consumer is the tf32 GEMM -> round at producer (rna)
        g_hin[(size_t)row * H_ + h] = tf32r((y[j] - mu) * rstd * gs[h] + es[h]);
    }
}

// ============ K2: xg = in @ Wih^T + bias   (mma.sync tf32) ============
// grid 148 = 2 n-halves x 74 m-slots. CTA: 256 thr, tile 128M x 256N, K=128.
// warps 2(m) x 4(n), each 64x64 via m16n8k8 frags (4x8).
// smem: As [128][132] 67584B | Bs [256][132] 135168B | bias 1KB  = 203776B
#define GXG_OFF_B   67584
#define GXG_OFF_BI  202752
#define GXG_SMEM    203776
#define N_MTILES    ((B_ * T_) / 128)   // 5760

__global__ void __launch_bounds__(256, 1) gemm_xg_kernel(
    const float* __restrict__ Wih0, const float* __restrict__ Wih1, int layer) {
    extern __shared__ char smem[];
    float* As    = (float*)smem;
    float* Bs    = (float*)(smem + GXG_OFF_B);
    float* biasS = (float*)(smem + GXG_OFF_BI);
    const uint32_t asAddr = smem_u32(As);

    const int tid  = threadIdx.x;
    const int lane = tid & 31, wid = tid >> 5;
    const int wm = wid & 1, wn = wid >> 1;         // warp grid 2m x 4n
    const int lrow = lane >> 2, lcol = lane & 3;
    const int nh = blockIdx.x & 1, slot = blockIdx.x >> 1;

    const float* in = layer ? g_hout0 : g_hin;
    const float* W  = (layer ? Wih1 : Wih0) + (size_t)nh * 256 * H_;

    // ---- one-time: weights -> smem (tf32-rounded), bias ----
    for (int idx = tid; idx < 256 * H_; idx += 256) {
        int n = idx >> 7, k = idx & 127;
        Bs[n * 132 + k] = tf32r(W[(size_t)n * H_ + k]);
    }
    for (int i = tid; i < 256; i += 256) biasS[i] = g_biasC[layer * G_ + nh * 256 + i];
    __syncthreads();

    // bias cached per-thread for epilogue (per nf, cols 2*lcol, 2*lcol+1)
    float bC[8][2];
#pragma unroll
    for (int nf = 0; nf < 8; nf++) {
        int c = wn * 64 + nf * 8 + 2 * lcol;
        bC[nf][0] = biasS[c];
        bC[nf][1] = biasS[c + 1];
    }

    auto copyA = [&](int m0) {
#pragma unroll 4
        for (int u = tid; u < 4096; u += 256) {
            int r = u >> 5, q = u & 31;
            cpa16(asAddr + (uint32_t)(r * 132 + q * 4) * 4,
                  in + (size_t)(m0 + r) * H_ + q * 4);
        }
        cpcommit();
    };

    int mt = slot;
    if (mt < N_MTILES) copyA(mt * 128);
    for (; mt < N_MTILES; mt += 74) {
        const int m0 = mt * 128;
        cpwait0();
        __syncthreads();

        float acc[4][8][4];
#pragma unroll
        for (int mf = 0; mf < 4; mf++)
#pragma unroll
            for (int nf = 0; nf < 8; nf++)
#pragma unroll
                for (int q = 0; q < 4; q++) acc[mf][nf][q] = 0.0f;

        const float* Aw = As + (wm * 64 + lrow) * 132 + lcol;
        const float* Bw = Bs + (wn * 64 + lrow) * 132 + lcol;
#pragma unroll
        for (int ks = 0; ks < 16; ks++) {
            const int k0 = ks * 8;
            uint32_t a[4][4], b[8][2];
#pragma unroll
            for (int mf = 0; mf < 4; mf++) {
                const float* p = Aw + mf * 16 * 132 + k0;
                a[mf][0] = __float_as_uint(p[0]);
                a[mf][1] = __float_as_uint(p[8 * 132]);
                a[mf][2] = __float_as_uint(p[4]);
                a[mf][3] = __float_as_uint(p[8 * 132 + 4]);
            }
#pragma unroll
            for (int nf = 0; nf < 8; nf++) {
                const float* p = Bw + nf * 8 * 132 + k0;
                b[nf][0] = __float_as_uint(p[0]);
                b[nf][1] = __float_as_uint(p[4]);
            }
#pragma unroll
            for (int mf = 0; mf < 4; mf++)
#pragma unroll
                for (int nf = 0; nf < 8; nf++)
                    mma_tf32(acc[mf][nf], a[mf], b[nf]);
        }
        __syncthreads();                 // all warps done reading As
        if (mt + 74 < N_MTILES) copyA((mt + 74) * 128);   // overlaps epilogue

        // ---- epilogue: bias add + store ----
#pragma unroll
        for (int mf = 0; mf < 4; mf++) {
            int r0 = m0 + wm * 64 + mf * 16 + lrow;
            float* o0 = g_xg + (size_t)r0 * G_ + nh * 256 + wn * 64;
            float* o1 = o0 + (size_t)8 * G_;
#pragma unroll
            for (int nf = 0; nf < 8; nf++) {
                int c = nf * 8 + 2 * lcol;
                float2 v0 = make_float2(acc[mf][nf][0] + bC[nf][0],
                                        acc[mf][nf][1] + bC[nf][1]);
                float2 v1 = make_float2(acc[mf][nf][2] + bC[nf][0],
                                        acc[mf][nf][3] + bC[nf][1]);
                *(float2*)(o0 + c) = v0;
                *(float2*)(o1 + c) = v1;
            }
        }
    }
}

// ============ K3: sequential recurrence (K=128) + LN + dense head ============
// 128 CTAs x 256 threads, 64 batch rows per CTA.
// smem: aT 32KB (h, k-major [128][64]) | wbuf0 64KB | wbuf1 64KB = 160KB
#define SQ_OFF_W0  32768
#define SQ_OFF_W1  (32768 + 65536)
#define SQ_SMEM    163840

__global__ void __launch_bounds__(256, 1) lstm_seq_kernel(
    int layer,
    const float* __restrict__ g_ln, const float* __restrict__ be_ln,
    const float* __restrict__ W_d1, const float* __restrict__ b_d1,
    const float* __restrict__ W_d2, const float* __restrict__ b_d2,
    const float* __restrict__ W_d3, const float* __restrict__ b_d3,
    float* __restrict__ out) {
    extern __shared__ char smem[];
    float* aT    = (float*)smem;
    float* wbuf0 = (float*)(smem + SQ_OFF_W0);
    float* wbuf1 = (float*)(smem + SQ_OFF_W1);

    const int tid = threadIdx.x;
    const int tr  = tid & 15;   // rows 4*tr .. 4*tr+3
    const int tc  = tid >> 4;   // cols [tc*8, tc*8+8) within each gate
    const int row0 = blockIdx.x * 64;
    const float* WT = g_WTh + layer * (H_ * G_);

    uint32_t wsmAddr[2];
    wsmAddr[0] = smem_u32(wbuf0);
    wsmAddr[1] = smem_u32(wbuf1);

    unsigned long long c2[4][4];
    unsigned long long acc[4][4][4];

    for (int i = tid; i < H_ * 64; i += 256) aT[i] = 0.0f;   // h = 0
#pragma unroll
    for (int i = 0; i < 4; i++)
#pragma unroll
        for (int p = 0; p < 4; p++) c2[i][p] = 0ull;
    __syncthreads();

    auto issue_copy = [&](int ck) {
        const float* src = WT + ck * (32 * G_);
        uint32_t sbuf = wsmAddr[ck & 1];
#pragma unroll
        for (int j = 0; j < 16; j++) {
            int u = tid + 256 * j;
            cpa16(sbuf + u * 16, src + u * 4);
        }
        cpcommit();
    };
    const int tc2 = tc * 2;

    for (int t = 0; t < T_; ++t) {
        // ---- acc <- xg (bias already folded in) ----
#pragma unroll
        for (int i = 0; i < 4; i++) {
            int r = tr * 4 + i;
            const float* p = g_xg + ((size_t)(row0 + r) * T_ + t) * G_ + tc * 8;
#pragma unroll
            for (int g = 0; g < 4; g++) {
                float4 v0 = *(const float4*)(p + g * 128);
                float4 v1 = *(const float4*)(p + g * 128 + 4);
                acc[i][g][0] = pkab(v0.x, v0.y);
                acc[i][g][1] = pkab(v0.z, v0.w);
                acc[i][g][2] = pkab(v1.x, v1.y);
                acc[i][g][3] = pkab(v1.z, v1.w);
            }
        }
        if (t) {
            // ---- h @ Whh^T: 4 chunks of 32 k, double-buffered cp.async ----
            issue_copy(0);
            for (int ck = 0; ck < 4; ++ck) {
                cpwait0();
                __syncthreads();
                if (ck < 3) issue_copy(ck + 1);
                const float* wb  = (ck & 1) ? wbuf1 : wbuf0;
                const float* aTk = aT + ck * (32 * 64);
#pragma unroll 4
                for (int kk = 0; kk < 32; ++kk) {
                    const float4 a4 = *(const float4*)(aTk + kk * 64 + tr * 4);
                    unsigned long long a2[4] = {pk2(a4.x), pk2(a4.y), pk2(a4.z), pk2(a4.w)};
                    const ulonglong2* wr = (const ulonglong2*)(wb + kk * G_);
#pragma unroll
                    for (int g = 0; g < 4; ++g) {
                        ulonglong2 wA = wr[g * 32 + tc2];
                        ulonglong2 wB = wr[g * 32 + tc2 + 1];
#pragma unroll
                        for (int i = 0; i < 4; ++i) {
                            fma2(acc[i][g][0], a2[i], wA.x);
                            fma2(acc[i][g][1], a2[i], wA.y);
                            fma2(acc[i][g][2], a2[i], wB.x);
                            fma2(acc[i][g][3], a2[i], wB.y);
                        }
                    }
                }
            }
        }
        __syncthreads();   // all GEMM reads of aT done before h overwrite

        // ---- activations + state update ----
#pragma unroll
        for (int i = 0; i < 4; i++) {
            int r = tr * 4 + i;
            float hv[8];
#pragma unroll
            for (int p = 0; p < 4; p++) {
                float iv0, iv1, fv0, fv1, gv0, gv1, ov0, ov1;
                up2(acc[i][0][p], iv0, iv1);
                up2(acc[i][1][p], fv0, fv1);
                up2(acc[i][2][p], gv0, gv1);
                up2(acc[i][3][p], ov0, ov1);
                float c0, c1;
                up2(c2[i][p], c0, c1);
                c0 = sgf(fv0) * c0 + sgf(iv0) * thf(gv0);
                c1 = sgf(fv1) * c1 + sgf(iv1) * thf(gv1);
                c2[i][p] = pkab(c0, c1);
                float h0 = sgf(ov0) * thf(c0);
                float h1 = sgf(ov1) * thf(c1);
                int col = tc * 8 + 2 * p;
                aT[col * 64 + r]       = h0;
                aT[(col + 1) * 64 + r] = h1;
                hv[2 * p] = h0; hv[2 * p + 1] = h1;
            }
            if (layer == 0) {
                // only consumer is the tf32 GEMM -> round at producer (rna)
                float* dst = g_hout0 + ((size_t)(row0 + r) * T_ + t) * H_ + tc * 8;
                *(float4*)(dst)     = make_float4(tf32r(hv[0]), tf32r(hv[1]),
                                                  tf32r(hv[2]), tf32r(hv[3]));
                *(float4*)(dst + 4) = make_float4(tf32r(hv[4]), tf32r(hv[5]),
                                                  tf32r(hv[6]), tf32r(hv[7]));
            }
        }
        __syncthreads();   // h ready for next step's GEMM
    } // t

    if (layer == 0) return;

    // =================== dense head (final h lives in aT) ===================
    float* lnS = (float*)(smem + SQ_OFF_W0);            // [64][128]
    float* d1S = (float*)(smem + SQ_OFF_W0 + 32768);    // [64][128]
    float* wdS = (float*)(smem + SQ_OFF_W0 + 65536);    // weight staging (64KB)
    float* d2S = lnS;

    if (tid < 64) {
        int r = tid;
        float s = 0.0f;
        for (int k = 0; k < H_; k++) s += aT[k * 64 + r];
        float mu = s * (1.0f / H_);
        float v = 0.0f;
        for (int k = 0; k < H_; k++) { float d = aT[k * 64 + r] - mu; v += d * d; }
        float rstd = rsqrtf(v * (1.0f / H_) + 1e-5f);
        for (int k = 0; k < H_; k++)
            lnS[r * H_ + k] = (aT[k * 64 + r] - mu) * rstd * __ldg(g_ln + k) + __ldg(be_ln + k);
    }
    for (int i = tid; i < D1_ * H_ / 4; i += 256)
        ((float4*)wdS)[i] = ((const float4*)W_d1)[i];
    __syncthreads();

    {
        int r = tid >> 2, c0 = (tid & 3) * 32;
        for (int c = c0; c < c0 + 32; c++) {
            float a = __ldg(b_d1 + c);
            const float4* lp = (const float4*)(lnS + r * H_);
            const float4* wp = (const float4*)(wdS + c * H_);
#pragma unroll 8
            for (int k4 = 0; k4 < H_ / 4; k4++) {
                float4 l = lp[k4], w = wp[k4];
                a = fmaf(l.x, w.x, fmaf(l.y, w.y, fmaf(l.z, w.z, fmaf(l.w, w.w, a))));
            }
            d1S[r * D1_ + c] = fmaxf(a, 0.0f);
        }
    }
    __syncthreads();
    for (int i = tid; i < D2_ * D1_ / 4; i += 256)
        ((float4*)wdS)[i] = ((const float4*)W_d2)[i];
    float* w3S = wdS + D2_ * D1_;
    for (int i = tid; i < OUT_ * D2_; i += 256) w3S[i] = W_d3[i];
    __syncthreads();

    {
        int r = tid >> 2, c0 = (tid & 3) * 16;
        for (int c = c0; c < c0 + 16; c++) {
            float a = __ldg(b_d2 + c);
            const float4* dp = (const float4*)(d1S + r * D1_);
            const float4* wp = (const float4*)(wdS + c * D1_);
#pragma unroll 8
            for (int k4 = 0; k4 < D1_ / 4; k4++) {
                float4 l = dp[k4], w = wp[k4];
                a = fmaf(l.x, w.x, fmaf(l.y, w.y, fmaf(l.z, w.z, fmaf(l.w, w.w, a))));
            }
            d2S[r * D2_ + c] = fmaxf(a, 0.0f);
        }
    }
    __syncthreads();

    for (int idx = tid; idx < 64 * OUT_; idx += 256) {
        int r = idx / OUT_, c = idx % OUT_;
        float a = __ldg(b_d3 + c);
        const float* dp = d2S + r * D2_;
        const float* wp = w3S + c * D2_;
#pragma unroll 8
        for (int k = 0; k < D2_; k++) a = fmaf(dp[k], wp[k], a);
        out[(size_t)(row0 + r) * OUT_ + c] = a;
    }
}

// ======================= launch =======================
extern "C" void kernel_launch(void* const* d_in, const int* in_sizes, int n_in,
                              void* d_out, int out_size) {
    (void)in_sizes; (void)n_in; (void)out_size;
    const float* x     = (const float*)d_in[0];
    const float* W_in  = (const float*)d_in[1];
    const float* b_in  = (const float*)d_in[2];
    const float* g_in  = (const float*)d_in[3];
    const float* be_in = (const float*)d_in[4];
    const float* Wih0  = (const float*)d_in[5];
    const float* Whh0  = (const float*)d_in[6];
    const float* bih0  = (const float*)d_in[7];
    const float* bhh0  = (const float*)d_in[8];
    const float* Wih1  = (const float*)d_in[9];
    const float* Whh1  = (const float*)d_in[10];
    const float* bih1  = (const float*)d_in[11];
    const float* bhh1  = (const float*)d_in[12];
    const float* g_ln  = (const float*)d_in[13];
    const float* be_ln = (const float*)d_in[14];
    const float* W_d1  = (const float*)d_in[15];
    const float* b_d1  = (const float*)d_in[16];
    const float* W_d2  = (const float*)d_in[17];
    const float* b_d2  = (const float*)d_in[18];
    const float* W_d3  = (const float*)d_in[19];
    const float* b_d3  = (const float*)d_in[20];
    float* out = (float*)d_out;

    cudaFuncSetAttribute(gemm_xg_kernel, cudaFuncAttributeMaxDynamicSharedMemorySize, GXG_SMEM);
    cudaFuncSetAttribute(lstm_seq_kernel, cudaFuncAttributeMaxDynamicSharedMemorySize, SQ_SMEM);

    prep_kernel<<<512, 256>>>(Whh0, bih0, bhh0, Whh1, bih1, bhh1);
    proj_ln_kernel<<<(B_ * T_) / 8, 256>>>(x, W_in, b_in, g_in, be_in);

    gemm_xg_kernel<<<148, 256, GXG_SMEM>>>(Wih0, Wih1, 0);
    lstm_seq_kernel<<<B_ / 64, 256, SQ_SMEM>>>(0, g_ln, be_ln, W_d1, b_d1,
                                               W_d2, b_d2, W_d3, b_d3, out);
    gemm_xg_kernel<<<148, 256, GXG_SMEM>>>(Wih0, Wih1, 1);
    lstm_seq_kernel<<<B_ / 64, 256, SQ_SMEM>>>(1, g_ln, be_ln, W_d1, b_d1,
                                               W_d2, b_d2, W_d3, b_d3, out);
}

// round 11
// speedup vs baseline: 2.1469x; 1.4445x over previous
#include <cuda_runtime.h>
#include <cuda_bf16.h>
#include <cstdint>
#include <cstddef>

#define B_    8192
#define T_    90
#define F_    7
#define H_    128
#define G_    512      // 4*H
#define D1_   128
#define D2_   64
#define OUT_  30

// -------- device scratch (no cudaMalloc allowed) --------
__device__ __align__(128) float g_hin  [(size_t)B_ * T_ * H_];   // LN(x@W_in^T+b), tf32-rounded
__device__ __align__(128) float g_hout0[(size_t)B_ * T_ * H_];   // layer-0 h outs, tf32-rounded
__device__ __align__(128) float g_xg   [(size_t)B_ * T_ * G_];   // input projections (+bias), unit-major cols
// Whh packed bf16 hi/lo k-pair fragments: [L][chunk 4][term 2][16][520] u32
__device__ __align__(128) uint32_t g_WP[2 * 4 * 2 * 16 * 520];
__device__ float g_biasC[2 * G_];   // bih + bhh, unit-major order

// ======================= common helpers =======================
__device__ __forceinline__ float sgf(float x) {
    return __fdividef(1.0f, 1.0f + __expf(-x));
}
__device__ __forceinline__ float thf(float x) {
    return 2.0f * sgf(2.0f * x) - 1.0f;
}
__device__ __forceinline__ float tf32r(float x) {
    uint32_t t;
    asm("cvt.rna.tf32.f32 %0, %1;" : "=r"(t) : "f"(x));
    return __uint_as_float(t);
}
__device__ __forceinline__ uint16_t bfb(float x) {
    __nv_bfloat16 b = __float2bfloat16(x);
    return *(uint16_t*)&b;
}
__device__ __forceinline__ float bff(uint16_t u) {
    __nv_bfloat16 b = *(__nv_bfloat16*)&u;
    return __bfloat162float(b);
}
__device__ __forceinline__ void cpa16(uint32_t s, const void* g) {
    asm volatile("cp.async.cg.shared.global [%0], [%1], 16;" :: "r"(s), "l"(g));
}
__device__ __forceinline__ void cpcommit() { asm volatile("cp.async.commit_group;"); }
__device__ __forceinline__ void cpwait0()  { asm volatile("cp.async.wait_group 0;"); }
__device__ __forceinline__ uint32_t smem_u32(const void* p) {
    uint32_t a;
    asm("{ .reg .u64 t; cvta.to.shared.u64 t, %1; cvt.u32.u64 %0, t; }" : "=r"(a) : "l"(p));
    return a;
}
// portable tensor-core mmas (sm_80+ PTX, run as HMMA on sm_103)
__device__ __forceinline__ void mma_tf32(float* d, const uint32_t* a, const uint32_t* b) {
    asm("mma.sync.aligned.m16n8k8.row.col.f32.tf32.tf32.f32 "
        "{%0,%1,%2,%3}, {%4,%5,%6,%7}, {%8,%9}, {%0,%1,%2,%3};"
        : "+f"(d[0]), "+f"(d[1]), "+f"(d[2]), "+f"(d[3])
        : "r"(a[0]), "r"(a[1]), "r"(a[2]), "r"(a[3]), "r"(b[0]), "r"(b[1]));
}
__device__ __forceinline__ void mma_bf16(float* d, const uint32_t* a, const uint32_t* b) {
    asm("mma.sync.aligned.m16n8k16.row.col.f32.bf16.bf16.f32 "
        "{%0,%1,%2,%3}, {%4,%5,%6,%7}, {%8,%9}, {%0,%1,%2,%3};"
        : "+f"(d[0]), "+f"(d[1]), "+f"(d[2]), "+f"(d[3])
        : "r"(a[0]), "r"(a[1]), "r"(a[2]), "r"(a[3]), "r"(b[0]), "r"(b[1]));
}

// ======================= K0: weight repack =======================
// n_phys = unit*4 + gate (gate: 0=i,1=f,2=g,3=o); source row = gate*128 + unit.
// g_WP[L][c][term][kk][520]: u32 = pack(bf16 W[k0], bf16 W[k0+1]), k0 = c*32+kk*2,
// where the "k" dim is the hidden-unit (contraction) index of h@Whh^T.
__global__ void prep_kernel(const float* __restrict__ Whh0, const float* __restrict__ bih0,
                            const float* __restrict__ bhh0, const float* __restrict__ Whh1,
                            const float* __restrict__ bih1, const float* __restrict__ bhh1) {
    int idx = blockIdx.x * blockDim.x + threadIdx.x;
    const int per_l = 4 * 16 * 520;
    if (idx < 2 * per_l) {
        int L = idx / per_l;
        int r = idx % per_l;
        int c = r / (16 * 520);
        int kk = (r / 520) % 16;
        int n = r % 520;
        uint32_t phi = 0, plo = 0;
        if (n < 512) {
            const float* Whh = L ? Whh1 : Whh0;
            int u = n >> 2, g = n & 3;
            const float* src = Whh + (size_t)(g * 128 + u) * H_ + (c * 32 + kk * 2);
            float w0 = src[0], w1 = src[1];
            uint16_t h0 = bfb(w0), h1 = bfb(w1);
            uint16_t l0 = bfb(w0 - bff(h0)), l1 = bfb(w1 - bff(h1));
            phi = ((uint32_t)h1 << 16) | h0;
            plo = ((uint32_t)l1 << 16) | l0;
        }
        int base = ((L * 4 + c) * 2) * (16 * 520) + kk * 520 + n;
        g_WP[base] = phi;
        g_WP[base + 16 * 520] = plo;
    }
    if (idx < 2 * G_) {
        int L = idx >> 9, n = idx & 511;
        int u = n >> 2, g = n & 3;
        const float* bih = L ? bih1 : bih0;
        const float* bhh = L ? bhh1 : bhh0;
        g_biasC[idx] = bih[g * 128 + u] + bhh[g * 128 + u];
    }
}

// ============ K1: input projection + layernorm (warp per row) ============
__global__ void __launch_bounds__(256) proj_ln_kernel(
    const float* __restrict__ x, const float* __restrict__ W_in,
    const float* __restrict__ b_in, const float* __restrict__ g_in,
    const float* __restrict__ be_in) {
    __shared__ float Ws[H_ * F_];
    __shared__ float bs[H_], gs[H_], es[H_];
    int tid = threadIdx.x;
    for (int i = tid; i < H_ * F_; i += 256) Ws[i] = W_in[i];
    if (tid < H_) { bs[tid] = b_in[tid]; gs[tid] = g_in[tid]; es[tid] = be_in[tid]; }
    __syncthreads();

    int warp = tid >> 5, lane = tid & 31;
    int row = blockIdx.x * 8 + warp;

    float xv = (lane < F_) ? x[(size_t)row * F_ + lane] : 0.0f;
    float y[4];
#pragma unroll
    for (int j = 0; j < 4; j++) {
        int h = lane + 32 * j;
        float a = bs[h];
#pragma unroll
        for (int f = 0; f < F_; f++) {
            float xf = __shfl_sync(0xffffffffu, xv, f);
            a = fmaf(xf, Ws[h * F_ + f], a);
        }
        y[j] = a;
    }
    float s = y[0] + y[1] + y[2] + y[3];
#pragma unroll
    for (int o = 16; o; o >>= 1) s += __shfl_xor_sync(0xffffffffu, s, o);
    float mu = s * (1.0f / H_);
    float v = 0.0f;
#pragma unroll
    for (int j = 0; j < 4; j++) { float d = y[j] - mu; v += d * d; }
#pragma unroll
    for (int o = 16; o; o >>= 1) v += __shfl_xor_sync(0xffffffffu, v, o);
    float rstd = rsqrtf(v * (1.0f / H_) + 1e-5f);
#pragma unroll
    for (int j = 0; j < 4; j++) {
        int h = lane + 32 * j;
        g_hin[(size_t)row * H_ + h] = tf32r((y[j] - mu) * rstd * gs[h] + es[h]);
    }
}

// ============ K2: xg = in @ Wih^T + bias   (mma.sync tf32, unit-major cols) ============
#define GXG_OFF_B   67584
#define GXG_OFF_BI  202752
#define GXG_SMEM    203776
#define N_MTILES    ((B_ * T_) / 128)   // 5760

__global__ void __launch_bounds__(256, 1) gemm_xg_kernel(
    const float* __restrict__ Wih0, const float* __restrict__ Wih1, int layer) {
    extern __shared__ char smem[];
    float* As    = (float*)smem;
    float* Bs    = (float*)(smem + GXG_OFF_B);
    float* biasS = (float*)(smem + GXG_OFF_BI);
    const uint32_t asAddr = smem_u32(As);

    const int tid  = threadIdx.x;
    const int lane = tid & 31, wid = tid >> 5;
    const int wm = wid & 1, wn = wid >> 1;
    const int lrow = lane >> 2, lcol = lane & 3;
    const int nh = blockIdx.x & 1, slot = blockIdx.x >> 1;

    const float* in = layer ? g_hout0 : g_hin;
    const float* W  = layer ? Wih1 : Wih0;   // full, indexed via n_phys mapping

    for (int idx = tid; idx < 256 * H_; idx += 256) {
        int n = idx >> 7, k = idx & 127;
        int np = nh * 256 + n;               // physical (unit-major) column
        Bs[n * 132 + k] = tf32r(W[(size_t)((np & 3) * 128 + (np >> 2)) * H_ + k]);
    }
    for (int i = tid; i < 256; i += 256) biasS[i] = g_biasC[layer * G_ + nh * 256 + i];
    __syncthreads();

    float bC[8][2];
#pragma unroll
    for (int nf = 0; nf < 8; nf++) {
        int c = wn * 64 + nf * 8 + 2 * lcol;
        bC[nf][0] = biasS[c];
        bC[nf][1] = biasS[c + 1];
    }

    auto copyA = [&](int m0) {
#pragma unroll 4
        for (int u = tid; u < 4096; u += 256) {
            int r = u >> 5, q = u & 31;
            cpa16(asAddr + (uint32_t)(r * 132 + q * 4) * 4,
                  in + (size_t)(m0 + r) * H_ + q * 4);
        }
        cpcommit();
    };

    int mt = slot;
    if (mt < N_MTILES) copyA(mt * 128);
    for (; mt < N_MTILES; mt += 74) {
        const int m0 = mt * 128;
        cpwait0();
        __syncthreads();

        float acc[4][8][4];
#pragma unroll
        for (int mf = 0; mf < 4; mf++)
#pragma unroll
            for (int nf = 0; nf < 8; nf++)
#pragma unroll
                for (int q = 0; q < 4; q++) acc[mf][nf][q] = 0.0f;

        const float* Aw = As + (wm * 64 + lrow) * 132 + lcol;
        const float* Bw = Bs + (wn * 64 + lrow) * 132 + lcol;
#pragma unroll
        for (int ks = 0; ks < 16; ks++) {
            const int k0 = ks * 8;
            uint32_t a[4][4], b[8][2];
#pragma unroll
            for (int mf = 0; mf < 4; mf++) {
                const float* p = Aw + mf * 16 * 132 + k0;
                a[mf][0] = __float_as_uint(p[0]);
                a[mf][1] = __float_as_uint(p[8 * 132]);
                a[mf][2] = __float_as_uint(p[4]);
                a[mf][3] = __float_as_uint(p[8 * 132 + 4]);
            }
#pragma unroll
            for (int nf = 0; nf < 8; nf++) {
                const float* p = Bw + nf * 8 * 132 + k0;
                b[nf][0] = __float_as_uint(p[0]);
                b[nf][1] = __float_as_uint(p[4]);
            }
#pragma unroll
            for (int mf = 0; mf < 4; mf++)
#pragma unroll
                for (int nf = 0; nf < 8; nf++)
                    mma_tf32(acc[mf][nf], a[mf], b[nf]);
        }
        __syncthreads();
        if (mt + 74 < N_MTILES) copyA((mt + 74) * 128);

#pragma unroll
        for (int mf = 0; mf < 4; mf++) {
            int r0 = m0 + wm * 64 + mf * 16 + lrow;
            float* o0 = g_xg + (size_t)r0 * G_ + nh * 256 + wn * 64;
            float* o1 = o0 + (size_t)8 * G_;
#pragma unroll
            for (int nf = 0; nf < 8; nf++) {
                int c = nf * 8 + 2 * lcol;
                float2 v0 = make_float2(acc[mf][nf][0] + bC[nf][0],
                                        acc[mf][nf][1] + bC[nf][1]);
                float2 v1 = make_float2(acc[mf][nf][2] + bC[nf][0],
                                        acc[mf][nf][3] + bC[nf][1]);
                *(float2*)(o0 + c) = v0;
                *(float2*)(o1 + c) = v1;
            }
        }
    }
}

// ============ K3: sequential recurrence (bf16 3-term mma) + LN + dense head ============
// 128 CTAs x 256 threads (8 warps, 1m x 8n), 64 batch rows per CTA.
// smem map:
//   [0,17408)        AP hi  u32[64][68]   (h packed bf16 pairs, k = unit)
//   [17408,34816)    AP lo
//   [34816,68608)    hstage f32[64][132]  (fp32 h for g_hout0 store / dense head)
//   [68608,135168)   wbuf0: [term2][16][520] u32
//   [135168,201728)  wbuf1
#define APHI_OFF   0
#define APLO_OFF   17408
#define HST_OFF    34816
#define HSTRIDE    132
#define WB0_OFF    68608
#define WB1_OFF    135168
#define WTERM_U32  (16 * 520)
#define WCHUNK_B   (2 * 16 * 520 * 4)   // 66560
#define SQ_SMEM    201728

__global__ void __launch_bounds__(256, 1) lstm_seq_kernel(
    int layer,
    const float* __restrict__ g_ln, const float* __restrict__ be_ln,
    const float* __restrict__ W_d1, const float* __restrict__ b_d1,
    const float* __restrict__ W_d2, const float* __restrict__ b_d2,
    const float* __restrict__ W_d3, const float* __restrict__ b_d3,
    float* __restrict__ out) {
    extern __shared__ char smem[];
    float* hstage = (float*)(smem + HST_OFF);
    const uint32_t* aphi = (const uint32_t*)(smem + APHI_OFF);
    const uint32_t* aplo = (const uint32_t*)(smem + APLO_OFF);

    const int tid = threadIdx.x;
    const int lane = tid & 31, wn = tid >> 5;
    const int qid = lane >> 2, j = lane & 3;
    const int row0 = blockIdx.x * 64;
    const uint32_t sb = smem_u32(smem);
    const uint32_t* wpL = g_WP + (size_t)layer * 4 * 2 * WTERM_U32;

    float acc[4][8][4];
    float cst[4][8];
#pragma unroll
    for (int mf = 0; mf < 4; mf++)
#pragma unroll
        for (int nt = 0; nt < 8; nt++) cst[mf][nt] = 0.0f;

    auto issue_copy = [&](int c) {
        const float4* src = (const float4*)(wpL + (size_t)c * 2 * WTERM_U32);
        uint32_t dst = sb + ((c & 1) ? WB1_OFF : WB0_OFF);
        for (int u = tid; u < WCHUNK_B / 16; u += 256)
            cpa16(dst + u * 16, src + u);
        cpcommit();
    };

    for (int t = 0; t < T_; ++t) {
        // ---- acc <- xg (unit-major, bias folded) ----
#pragma unroll
        for (int mf = 0; mf < 4; mf++) {
            const float* x1 = g_xg + ((size_t)(row0 + mf * 16 + qid) * T_ + t) * G_;
            const float* x2 = x1 + (size_t)8 * T_ * G_;
#pragma unroll
            for (int nt = 0; nt < 8; nt++) {
                int c = wn * 64 + nt * 8 + 2 * j;
                float2 v1 = *(const float2*)(x1 + c);
                float2 v2 = *(const float2*)(x2 + c);
                acc[mf][nt][0] = v1.x; acc[mf][nt][1] = v1.y;
                acc[mf][nt][2] = v2.x; acc[mf][nt][3] = v2.y;
            }
        }
        // ---- layer-0: stream previous step's h to global (coalesced) ----
        if (layer == 0 && t > 0) {
#pragma unroll
            for (int k = 0; k < 8; k++) {
                int idx = tid + k * 256;
                int r = idx >> 5, c4 = (idx & 31) * 4;
                float4 v = *(const float4*)(hstage + r * HSTRIDE + c4);
                *(float4*)(g_hout0 + ((size_t)(row0 + r) * T_ + (t - 1)) * H_ + c4) = v;
            }
        }
        // ---- h @ Whh^T via bf16 3-term mma, 4 streamed weight chunks ----
        if (t) {
            for (int c = 0; c < 4; ++c) {
                cpwait0();
                __syncthreads();
                if (c < 3) issue_copy(c + 1);
                const uint32_t* whi = (const uint32_t*)(smem + ((c & 1) ? WB1_OFF : WB0_OFF));
                const uint32_t* wlo = whi + WTERM_U32;
#pragma unroll
                for (int lkt = 0; lkt < 2; ++lkt) {
                    const int kb = c * 16 + lkt * 8 + j;
                    uint32_t ah[4][4], al[4][4];
#pragma unroll
                    for (int mf = 0; mf < 4; ++mf) {
                        const uint32_t* p1 = aphi + (mf * 16 + qid) * 68;
                        const uint32_t* p2 = p1 + 8 * 68;
                        ah[mf][0] = p1[kb];     ah[mf][1] = p2[kb];
                        ah[mf][2] = p1[kb + 4]; ah[mf][3] = p2[kb + 4];
                        const uint32_t* q1 = aplo + (mf * 16 + qid) * 68;
                        const uint32_t* q2 = q1 + 8 * 68;
                        al[mf][0] = q1[kb];     al[mf][1] = q2[kb];
                        al[mf][2] = q1[kb + 4]; al[mf][3] = q2[kb + 4];
                    }
                    const uint32_t* wh0 = whi + (lkt * 8 + j) * 520;
                    const uint32_t* wh1 = wh0 + 4 * 520;
                    const uint32_t* wl0 = wlo + (lkt * 8 + j) * 520;
                    const uint32_t* wl1 = wl0 + 4 * 520;
#pragma unroll
                    for (int nt = 0; nt < 8; ++nt) {
                        int n = wn * 64 + nt * 8 + qid;
                        uint32_t bh[2] = { wh0[n], wh1[n] };
                        uint32_t bl[2] = { wl0[n], wl1[n] };
#pragma unroll
                        for (int mf = 0; mf < 4; ++mf) mma_bf16(acc[mf][nt], ah[mf], bh);
#pragma unroll
                        for (int mf = 0; mf < 4; ++mf) mma_bf16(acc[mf][nt], al[mf], bh);
#pragma unroll
                        for (int mf = 0; mf < 4; ++mf) mma_bf16(acc[mf][nt], ah[mf], bl);
                    }
                }
            }
        }
        __syncthreads();   // mma done reading AP before rewrite; hstage STG reads done

        // ---- activations: shfl-pair (i,f)<->(g,o), update c, emit h ----
        const bool ev = (lane & 1) == 0;
        const bool keep_h = (layer == 0) || (t == T_ - 1);
#pragma unroll
        for (int mf = 0; mf < 4; ++mf) {
            int r1 = mf * 16 + qid;
#pragma unroll
            for (int nt = 0; nt < 8; ++nt) {
                float x0 = __shfl_xor_sync(0xffffffffu, acc[mf][nt][0], 1);
                float x1 = __shfl_xor_sync(0xffffffffu, acc[mf][nt][1], 1);
                float x2 = __shfl_xor_sync(0xffffffffu, acc[mf][nt][2], 1);
                float x3 = __shfl_xor_sync(0xffffffffu, acc[mf][nt][3], 1);
                float iv = ev ? acc[mf][nt][0] : x2;
                float fv = ev ? acc[mf][nt][1] : x3;
                float gv = ev ? x0 : acc[mf][nt][2];
                float ov = ev ? x1 : acc[mf][nt][3];
                float c = cst[mf][nt];
                c = sgf(fv) * c + sgf(iv) * thf(gv);
                cst[mf][nt] = c;
                float h = sgf(ov) * thf(c);
                int row = ev ? r1 : (r1 + 8);
                int u = wn * 16 + nt * 2 + ((lane >> 1) & 1);
                uint16_t hh = bfb(h);
                uint16_t hl = bfb(h - bff(hh));
                uint32_t off = (uint32_t)(row * 68 + (u >> 1)) * 4 + (u & 1) * 2;
                *(uint16_t*)(smem + APHI_OFF + off) = hh;
                *(uint16_t*)(smem + APLO_OFF + off) = hl;
                if (keep_h) hstage[row * HSTRIDE + u] = h;
            }
        }
        if (t + 1 < T_) issue_copy(0);   // prefetch chunk0 for next step
        __syncthreads();                 // AP/hstage ready
    } // t

    if (layer == 0) {
        // final h(T-1) -> g_hout0
#pragma unroll
        for (int k = 0; k < 8; k++) {
            int idx = tid + k * 256;
            int r = idx >> 5, c4 = (idx & 31) * 4;
            float4 v = *(const float4*)(hstage + r * HSTRIDE + c4);
            *(float4*)(g_hout0 + ((size_t)(row0 + r) * T_ + (T_ - 1)) * H_ + c4) = v;
        }
        return;
    }

    // =================== dense head (final h in hstage) ===================
    float* lnS = (float*)(smem + WB0_OFF);            // [64][128]
    float* d1S = (float*)(smem + WB0_OFF + 32768);    // [64][128]
    float* wdS = (float*)(smem + WB0_OFF + 65536);    // weight staging (64KB)
    float* d2S = lnS;

    if (tid < 64) {
        int r = tid;
        const float* hr = hstage + r * HSTRIDE;
        float s = 0.0f;
        for (int k = 0; k < H_; k++) s += hr[k];
        float mu = s * (1.0f / H_);
        float v = 0.0f;
        for (int k = 0; k < H_; k++) { float d = hr[k] - mu; v += d * d; }
        float rstd = rsqrtf(v * (1.0f / H_) + 1e-5f);
        for (int k = 0; k < H_; k++)
            lnS[r * H_ + k] = (hr[k] - mu) * rstd * __ldg(g_ln + k) + __ldg(be_ln + k);
    }
    for (int i = tid; i < D1_ * H_ / 4; i += 256)
        ((float4*)wdS)[i] = ((const float4*)W_d1)[i];
    __syncthreads();

    {
        int r = tid >> 2, c0 = (tid & 3) * 32;
        for (int c = c0; c < c0 + 32; c++) {
            float a = __ldg(b_d1 + c);
            const float4* lp = (const float4*)(lnS + r * H_);
            const float4* wp = (const float4*)(wdS + c * H_);
#pragma unroll 8
            for (int k4 = 0; k4 < H_ / 4; k4++) {
                float4 l = lp[k4], w = wp[k4];
                a = fmaf(l.x, w.x, fmaf(l.y, w.y, fmaf(l.z, w.z, fmaf(l.w, w.w, a))));
            }
            d1S[r * D1_ + c] = fmaxf(a, 0.0f);
        }
    }
    __syncthreads();
    for (int i = tid; i < D2_ * D1_ / 4; i += 256)
        ((float4*)wdS)[i] = ((const float4*)W_d2)[i];
    float* w3S = wdS + D2_ * D1_;
    for (int i = tid; i < OUT_ * D2_; i += 256) w3S[i] = W_d3[i];
    __syncthreads();

    {
        int r = tid >> 2, c0 = (tid & 3) * 16;
        for (int c = c0; c < c0 + 16; c++) {
            float a = __ldg(b_d2 + c);
            const float4* dp = (const float4*)(d1S + r * D1_);
            const float4* wp = (const float4*)(wdS + c * D1_);
#pragma unroll 8
            for (int k4 = 0; k4 < D1_ / 4; k4++) {
                float4 l = dp[k4], w = wp[k4];
                a = fmaf(l.x, w.x, fmaf(l.y, w.y, fmaf(l.z, w.z, fmaf(l.w, w.w, a))));
            }
            d2S[r * D2_ + c] = fmaxf(a, 0.0f);
        }
    }
    __syncthreads();

    for (int idx = tid; idx < 64 * OUT_; idx += 256) {
        int r = idx / OUT_, c = idx % OUT_;
        float a = __ldg(b_d3 + c);
        const float* dp = d2S + r * D2_;
        const float* wp = w3S + c * D2_;
#pragma unroll 8
        for (int k = 0; k < D2_; k++) a = fmaf(dp[k], wp[k], a);
        out[(size_t)(row0 + r) * OUT_ + c] = a;
    }
}

// ======================= launch =======================
extern "C" void kernel_launch(void* const* d_in, const int* in_sizes, int n_in,
                              void* d_out, int out_size) {
    (void)in_sizes; (void)n_in; (void)out_size;
    const float* x     = (const float*)d_in[0];
    const float* W_in  = (const float*)d_in[1];
    const float* b_in  = (const float*)d_in[2];
    const float* g_in  = (const float*)d_in[3];
    const float* be_in = (const float*)d_in[4];
    const float* Wih0  = (const float*)d_in[5];
    const float* Whh0  = (const float*)d_in[6];
    const float* bih0  = (const float*)d_in[7];
    const float* bhh0  = (const float*)d_in[8];
    const float* Wih1  = (const float*)d_in[9];
    const float* Whh1  = (const float*)d_in[10];
    const float* bih1  = (const float*)d_in[11];
    const float* bhh1  = (const float*)d_in[12];
    const float* g_ln  = (const float*)d_in[13];
    const float* be_ln = (const float*)d_in[14];
    const float* W_d1  = (const float*)d_in[15];
    const float* b_d1  = (const float*)d_in[16];
    const float* W_d2  = (const float*)d_in[17];
    const float* b_d2  = (const float*)d_in[18];
    const float* W_d3  = (const float*)d_in[19];
    const float* b_d3  = (const float*)d_in[20];
    float* out = (float*)d_out;

    cudaFuncSetAttribute(gemm_xg_kernel, cudaFuncAttributeMaxDynamicSharedMemorySize, GXG_SMEM);
    cudaFuncSetAttribute(lstm_seq_kernel, cudaFuncAttributeMaxDynamicSharedMemorySize, SQ_SMEM);

    prep_kernel<<<264, 256>>>(Whh0, bih0, bhh0, Whh1, bih1, bhh1);
    proj_ln_kernel<<<(B_ * T_) / 8, 256>>>(x, W_in, b_in, g_in, be_in);

    gemm_xg_kernel<<<148, 256, GXG_SMEM>>>(Wih0, Wih1, 0);
    lstm_seq_kernel<<<B_ / 64, 256, SQ_SMEM>>>(0, g_ln, be_ln, W_d1, b_d1,
                                               W_d2, b_d2, W_d3, b_d3, out);
    gemm_xg_kernel<<<148, 256, GXG_SMEM>>>(Wih0, Wih1, 1);
    lstm_seq_kernel<<<B_ / 64, 256, SQ_SMEM>>>(1, g_ln, be_ln, W_d1, b_d1,
                                               W_d2, b_d2, W_d3, b_d3, out);
}